// round 1
// baseline (speedup 1.0000x reference)
#include <cuda_runtime.h>
#include <cuda_bf16.h>

// KinematicWaveRouting: per row, 20-segment linear kinematic-wave recurrence,
// outlet = Q[20] per timestep.
//   u      = runoff[b,t] * basin_area[b] * 50.0f        (all unit factors folded)
//   Q_i   <- (1-CFL)*Q_i + CFL*Q_{i-1} + u,  CFL = 0.9, Q_0 = 0
// max(.,0) dropped: all terms nonnegative, Q stays >= 0 exactly.
// manning_n / slope / width are unused by the reference.
//
// Time-chunked parallelization: thread = (row, chunk of 256 steps), warm-started
// from zero state HALO=32 steps early. Homogeneous-response decay makes the
// truncation error ~1e-5 relative (tolerance is 1e-3).

#define T_LEN   4096
#define NSEG    20
#define CHUNK   256
#define HALO    32
#define NCHUNK  (T_LEN / CHUNK)   // 16

__global__ __launch_bounds__(256, 8)
void kinematic_wave_kernel(const float* __restrict__ runoff,
                           const float* __restrict__ basin,
                           float* __restrict__ out,
                           int B)
{
    int gid   = blockIdx.x * blockDim.x + threadIdx.x;
    int row   = gid >> 4;          // / NCHUNK
    int chunk = gid & (NCHUNK - 1);
    if (row >= B) return;

    const float scale = basin[row] * 50.0f;
    const float cfl   = 0.9f;
    const float om    = 1.0f - 0.9f;   // 0.100000024f, matches ref's 1-CFL path closely

    float Q[NSEG + 1];
#pragma unroll
    for (int i = 0; i <= NSEG; i++) Q[i] = 0.0f;

    const float* rbase = runoff + (size_t)row * T_LEN + chunk * CHUNK;
    float*       obase = out    + (size_t)row * T_LEN + chunk * CHUNK;

    // ---- warm-up (halo) steps: advance state, no output ----
    if (chunk != 0) {
        const float4* rp = (const float4*)(rbase - HALO);
#pragma unroll 1
        for (int g = 0; g < HALO / 4; g++) {
            float4 r4 = rp[g];
            float uu[4] = {r4.x, r4.y, r4.z, r4.w};
#pragma unroll
            for (int k = 0; k < 4; k++) {
                float u = uu[k] * scale;
#pragma unroll
                for (int i = NSEG; i >= 1; i--) {
                    float t = fmaf(cfl, Q[i - 1], u);
                    Q[i] = fmaf(om, Q[i], t);
                }
            }
        }
    }

    // ---- main chunk: advance and emit outlet, 4 steps per float4 ----
    const float4* rp = (const float4*)rbase;
    float4*       op = (float4*)obase;
#pragma unroll 1
    for (int g = 0; g < CHUNK / 4; g++) {
        float4 r4 = rp[g];
        float uu[4] = {r4.x, r4.y, r4.z, r4.w};
        float o[4];
#pragma unroll
        for (int k = 0; k < 4; k++) {
            float u = uu[k] * scale;
#pragma unroll
            for (int i = NSEG; i >= 1; i--) {
                float t = fmaf(cfl, Q[i - 1], u);
                Q[i] = fmaf(om, Q[i], t);
            }
            o[k] = Q[NSEG];
        }
        op[g] = make_float4(o[0], o[1], o[2], o[3]);
    }
}

extern "C" void kernel_launch(void* const* d_in, const int* in_sizes, int n_in,
                              void* d_out, int out_size)
{
    const float* runoff = (const float*)d_in[0];   // (B, T) float32
    const float* basin  = (const float*)d_in[1];   // (B, 1) float32
    float* out = (float*)d_out;                    // (B, T) float32

    int B = in_sizes[1];                           // 8192
    int total = B * NCHUNK;
    int threads = 256;
    int blocks = (total + threads - 1) / threads;
    kinematic_wave_kernel<<<blocks, threads>>>(runoff, basin, out, B);
}

// round 2
// speedup vs baseline: 1.7702x; 1.7702x over previous
#include <cuda_runtime.h>
#include <cuda_bf16.h>

// KinematicWaveRouting on GB300.
//   u    = runoff[b,t] * basin_area[b] * 50.0f   (unit factors folded)
//   Q_i <- (1-CFL)*Q_i + CFL*Q_{i-1} + u,  CFL=0.9, Q_0=0,  outlet = Q_20
// max(.,0) is a no-op (all terms nonnegative). manning_n/slope/width unused.
//
// Layout: one WARP per row. Lane l owns time-chunk l (CHUNK=128 steps),
// warm-started HALO=32 steps early from zero state (truncation ~2e-7 rel).
// All global loads/stores are coalesced via a per-warp 32x33 smem transpose
// tile (conflict-free in every phase). Only __syncwarp needed.

#define T_LEN   4096
#define NSEG    20
#define CHUNK   128
#define NCHUNK  32
#define HALO    32
#define GROUPS  5          // (CHUNK + HALO) / 32
#define RPB     8          // rows (warps) per block

__global__ __launch_bounds__(256)
void kinematic_wave_kernel(const float* __restrict__ runoff,
                           const float* __restrict__ basin,
                           float* __restrict__ out,
                           int B)
{
    __shared__ float tile[RPB][NCHUNK][33];   // 33: conflict-free stride

    const int warp = threadIdx.x >> 5;
    const int lane = threadIdx.x & 31;
    const int row  = blockIdx.x * RPB + warp;
    if (row >= B) return;

    float (*tl)[33] = tile[warp];

    const float scale = basin[row] * 50.0f;
    const float cfl   = 0.9f;
    const float om    = 1.0f - 0.9f;          // folded, matches reference arithmetic

    float Q[NSEG + 1];
#pragma unroll
    for (int i = 0; i <= NSEG; i++) Q[i] = 0.0f;

    const float* rrow = runoff + (size_t)row * T_LEN;
    float*       orow = out    + (size_t)row * T_LEN;

#pragma unroll 1
    for (int g = 0; g < GROUPS; g++) {
        // ---- load phase: lane m fetches time (c*128 - 32 + g*32 + m) for every chunk c.
        //      Global access per c-iter: 32 consecutive floats -> one 128B coalesced LDG.
        //      STS tl[c][lane]: consecutive banks -> conflict-free.
        const int tbase = g * 32 + lane - HALO;
#pragma unroll 8
        for (int c = 0; c < NCHUNK; c++) {
            int t = c * CHUNK + tbase;                 // max = 4095, only t<0 possible OOB
            float v = (t >= 0) ? __ldg(rrow + t) : 0.0f;
            tl[c][lane] = v;
        }
        __syncwarp();

        // ---- compute phase: lane l advances its own chunk by 32 steps.
        //      LDS/STS tl[lane][m]: lane stride 33 -> all distinct banks.
        //      In-place overwrite with outlet value (only lane l touches row l).
#pragma unroll 8
        for (int m = 0; m < 32; m++) {
            float u = tl[lane][m] * scale;
#pragma unroll
            for (int i = NSEG; i >= 1; i--) {
                float t = fmaf(cfl, Q[i - 1], u);      // FFMA-imm (rt=1)
                Q[i] = fmaf(om, Q[i], t);              // FFMA-imm (rt=1)
            }
            tl[lane][m] = Q[NSEG];
        }
        __syncwarp();

        // ---- store phase (skip warm-up group): lane m writes chunk c's outlet
        //      at time c*128 + (g-1)*32 + m. Coalesced 128B STG per c-iter.
        if (g > 0) {
            const int obase = (g - 1) * 32 + lane;
#pragma unroll 8
            for (int c = 0; c < NCHUNK; c++) {
                orow[c * CHUNK + obase] = tl[c][lane];
            }
        }
        __syncwarp();   // outputs drained before next load overwrites the tile
    }
}

extern "C" void kernel_launch(void* const* d_in, const int* in_sizes, int n_in,
                              void* d_out, int out_size)
{
    const float* runoff = (const float*)d_in[0];   // (B, T) float32
    const float* basin  = (const float*)d_in[1];   // (B, 1) float32
    float* out = (float*)d_out;                    // (B, T) float32

    int B = in_sizes[1];                           // 8192
    int blocks = (B + RPB - 1) / RPB;              // 1024
    kinematic_wave_kernel<<<blocks, 256>>>(runoff, basin, out, B);
}

// round 3
// speedup vs baseline: 2.0803x; 1.1752x over previous
#include <cuda_runtime.h>
#include <cuda_bf16.h>

// KinematicWaveRouting via the scalar transfer function of the 20-segment chain.
//   State form:  Q_i <- 0.1*Q_i + 0.9*Q_{i-1} + u,  outlet = Q_20,  u = runoff*basin*50
//   LTI form:    outlet_t = sum_k u_k * g_{t-k},  g_m = P[Bin(m,0.9) <= 19]
//   Recurrence:  y_t = y_{t-1} + u_t - sum_{m=20..33} c_m * u_{t-m}
//                c_m = C(m-1,19) * 0.9^20 * 0.1^(m-20)   (NegBinomial pmf, sum = 1)
//   Truncation at m=33: tail ~1.3e-6 -> rel err ~1e-5 (tolerance 1e-3).
//   scale = basin*50 factored out (linearity), applied at the store.
// Layout identical to R2: one warp per row, lane = 128-step chunk, coalesced
// via 32x33 smem transpose tile; taps served from a register double-buffer.

#define T_LEN   4096
#define CHUNK   128
#define NCHUNK  32
#define RPB     8
#define NTAPS   14

// -c_m for m = 20..33
static __device__ constexpr float CNEG[NTAPS] = {
    -0.121576655f,  -0.243153309f,  -0.255310975f,  -0.187228048f,
    -0.107656128f,  -0.051674949f,  -0.021531222f,  -0.007997312f,
    -0.002699093f,  -0.000839712f,  -0.000243518f,  -0.000066414f,
    -0.0000171570f, -0.0000042233f
};
// g_m for m = 20..31 (warm-start FIR weights; g_m = 1 for m <= 19)
static __device__ constexpr float GW[12] = {
    0.878423345f, 0.635270036f, 0.379959062f, 0.192731014f,
    0.085074886f, 0.033399937f, 0.011868715f, 0.003871403f,
    0.001172310f, 0.000332598f, 0.000089080f, 0.000022666f
};

// One 32-step group: prev = previous 32 inputs, cur = current 32 inputs,
// carry = input 33 steps before group start (for the m=33 tap at step 0).
// Writes the 32 outlet values (unscaled) into the lane's tile row.
#define DO_GROUP(PREV, CUR)                                                 \
    do {                                                                    \
        _Pragma("unroll")                                                   \
        for (int m = 0; m < 32; m++) {                                      \
            float acc = CUR[m];                                             \
            _Pragma("unroll")                                               \
            for (int j = 0; j < NTAPS; j++) {                               \
                const int k = m - (20 + j);                                 \
                float w;                                                    \
                if (k >= 0)        w = CUR[k];                              \
                else if (k >= -32) w = PREV[32 + k];                        \
                else               w = carry;                               \
                acc = fmaf(CNEG[j], w, acc);                                \
            }                                                               \
            y += acc;                                                       \
            tlrow[m] = y;                                                   \
        }                                                                   \
    } while (0)

__global__ __launch_bounds__(256, 3)
void kinematic_wave_kernel(const float* __restrict__ runoff,
                           const float* __restrict__ basin,
                           float* __restrict__ out,
                           int B)
{
    __shared__ float tile[RPB][NCHUNK][33];   // [chunk][time], stride 33: conflict-free

    const int warp = threadIdx.x >> 5;
    const int lane = threadIdx.x & 31;
    const int row  = blockIdx.x * RPB + warp;
    if (row >= B) return;

    const float scale = basin[row] * 50.0f;
    const float* __restrict__ rrow = runoff + (size_t)row * T_LEN;
    float*       __restrict__ orow = out    + (size_t)row * T_LEN;
    float* tlrow = tile[warp][lane];

    float Abuf[32], Bbuf[32];
    float y, carry = 0.0f;

    // ---- warm group: load r[t0-32 .. t0-1] for every chunk (coalesced) ----
    {
        const int tb = lane - 32;
#pragma unroll 8
        for (int c = 0; c < NCHUNK; c++) {
            int t = c * CHUNK + tb;
            tile[warp][c][lane] = (t >= 0) ? __ldg(rrow + t) : 0.0f;
        }
    }
    __syncwarp();
#pragma unroll
    for (int j = 0; j < 32; j++) Abuf[j] = tlrow[j];
    // warm-start FIR: y = outlet at t0-1 (raw-input units)
    {
        float s = 0.0f;
#pragma unroll
        for (int j = 12; j < 32; j++) s += Abuf[j];        // lags 0..19, weight 1
        float s2 = 0.0f;
#pragma unroll
        for (int j = 0; j < 12; j++) s2 = fmaf(GW[11 - j], Abuf[j], s2);  // lags 20..31
        y = s + s2;
    }
    __syncwarp();

    // ---- 4 main groups of 32 steps, double-buffered prev/cur ----
#pragma unroll 1
    for (int gg = 0; gg < 2; gg++) {
        // --- group G = 2*gg+1: prev = Abuf, cur = Bbuf ---
        {
            const int tb = (2 * gg + 1) * 32 + lane - 32;   // >= 0 always
#pragma unroll 8
            for (int c = 0; c < NCHUNK; c++)
                tile[warp][c][lane] = __ldg(rrow + c * CHUNK + tb);
            __syncwarp();
#pragma unroll
            for (int j = 0; j < 32; j++) Bbuf[j] = tlrow[j];
            DO_GROUP(Abuf, Bbuf);
            carry = Abuf[31];                                // r_{T-1} of group G-1
            __syncwarp();
            const int ob = (2 * gg) * 32 + lane;
#pragma unroll 8
            for (int c = 0; c < NCHUNK; c++)
                orow[c * CHUNK + ob] = tile[warp][c][lane] * scale;
            __syncwarp();
        }
        // --- group G = 2*gg+2: prev = Bbuf, cur = Abuf ---
        {
            const int tb = (2 * gg + 2) * 32 + lane - 32;
#pragma unroll 8
            for (int c = 0; c < NCHUNK; c++)
                tile[warp][c][lane] = __ldg(rrow + c * CHUNK + tb);
            __syncwarp();
#pragma unroll
            for (int j = 0; j < 32; j++) Abuf[j] = tlrow[j];
            DO_GROUP(Bbuf, Abuf);
            carry = Bbuf[31];
            __syncwarp();
            const int ob = (2 * gg + 1) * 32 + lane;
#pragma unroll 8
            for (int c = 0; c < NCHUNK; c++)
                orow[c * CHUNK + ob] = tile[warp][c][lane] * scale;
            __syncwarp();
        }
    }
}

extern "C" void kernel_launch(void* const* d_in, const int* in_sizes, int n_in,
                              void* d_out, int out_size)
{
    const float* runoff = (const float*)d_in[0];   // (B, T) float32
    const float* basin  = (const float*)d_in[1];   // (B, 1) float32
    float* out = (float*)d_out;                    // (B, T) float32

    int B = in_sizes[1];                           // 8192
    int blocks = (B + RPB - 1) / RPB;              // 1024
    kinematic_wave_kernel<<<blocks, 256>>>(runoff, basin, out, B);
}

// round 5
// speedup vs baseline: 2.5110x; 1.2070x over previous
#include <cuda_runtime.h>
#include <cuda_bf16.h>

// KinematicWaveRouting via the scalar transfer function of the 20-segment chain.
//   y_t = y_{t-1} + u_t - sum_{m=20..31} c_m * u_{t-m},   u = runoff * basin * 50
//   c_m = C(m-1,19)*0.9^20*0.1^(m-20), renormalized so sum(c) = 1 exactly.
//   Max lag 31 -> prev-group window must cover indices 1..31 (FULL 32-reg
//   buffer; the R4 12-entry window was an out-of-bounds bug).
// One warp per row, lane = 128-step chunk, warm-started 32 steps early.
// Double-buffered smem transpose tile; group g+1's coalesced loads interleave
// with group g's compute (LDG early, dependent STS late, batches of 8).

#define T_LEN   4096
#define CHUNK   128
#define NCHUNK  32
#define RPB     4
#define NTAPS   12

// -c_m (renormalized), m = 20..31
static __device__ constexpr float CNEG[NTAPS] = {
    -0.12157942f, -0.24315882f, -0.25531676f, -0.18723229f,
    -0.10765857f, -0.05167612f, -0.02153171f, -0.00799749f,
    -0.00269915f, -0.00083973f, -0.00024352f, -0.00006643f
};
// g_m for m = 20..31 (warm-start FIR weights; g_m = 1 for m <= 19)
static __device__ constexpr float GW[12] = {
    0.878423345f, 0.635270036f, 0.379959062f, 0.192731014f,
    0.085074886f, 0.033399937f, 0.011868715f, 0.003871403f,
    0.001172310f, 0.000332598f, 0.000089080f, 0.000022666f
};

// One 32-step group. PREV[32] = previous group's inputs, CUR[32] = this
// group's inputs (loaded from TCUR row). Outputs overwrite TCUR[lane][m].
// If PREF, group GIDX+1's inputs are prefetched into TNXT (LDG early,
// STS late) interleaved with compute.
#define GROUP_BODY(PREV, CUR, TCUR, TNXT, GIDX, PREF)                       \
    do {                                                                    \
        float* tlrow = &TCUR[lane][0];                                      \
        _Pragma("unroll")                                                   \
        for (int j2 = 0; j2 < 32; j2++) CUR[j2] = tlrow[j2];                \
        _Pragma("unroll")                                                   \
        for (int p = 0; p < 4; p++) {                                       \
            float L[8];                                                     \
            if (PREF) {                                                     \
                _Pragma("unroll")                                           \
                for (int q = 0; q < 8; q++)                                 \
                    L[q] = __ldg(rrow + (p * 8 + q) * CHUNK                 \
                                      + (GIDX) * 32 + lane);                \
            }                                                               \
            _Pragma("unroll")                                               \
            for (int mm = 0; mm < 8; mm++) {                                \
                const int m = p * 8 + mm;                                   \
                float acc = CUR[m];                                         \
                _Pragma("unroll")                                           \
                for (int j = 0; j < NTAPS; j++) {                           \
                    const int k = m - (20 + j);                             \
                    float w = (k >= 0) ? CUR[k] : PREV[32 + k];             \
                    acc = fmaf(CNEG[j], w, acc);                            \
                }                                                           \
                y += acc;                                                   \
                tlrow[m] = y;                                               \
            }                                                               \
            if (PREF) {                                                     \
                _Pragma("unroll")                                           \
                for (int q = 0; q < 8; q++)                                 \
                    TNXT[p * 8 + q][lane] = L[q];                           \
            }                                                               \
        }                                                                   \
    } while (0)

#define DRAIN(TCUR, GIDX)                                                   \
    do {                                                                    \
        _Pragma("unroll 8")                                                 \
        for (int c = 0; c < NCHUNK; c++)                                    \
            orow[c * CHUNK + ((GIDX) - 1) * 32 + lane] =                    \
                TCUR[c][lane] * scale;                                      \
    } while (0)

__global__ __launch_bounds__(128, 5)
void kinematic_wave_kernel(const float* __restrict__ runoff,
                           const float* __restrict__ basin,
                           float* __restrict__ out,
                           int B)
{
    __shared__ float tile[2][RPB][NCHUNK][33];   // stride 33: conflict-free

    const int warp = threadIdx.x >> 5;
    const int lane = threadIdx.x & 31;
    const int row  = blockIdx.x * RPB + warp;
    if (row >= B) return;

    float (*T0)[33] = tile[0][warp];
    float (*T1)[33] = tile[1][warp];

    const float scale = basin[row] * 50.0f;
    const float* __restrict__ rrow = runoff + (size_t)row * T_LEN;
    float*       __restrict__ orow = out    + (size_t)row * T_LEN;

    float Abuf[32], Bbuf[32];
    float y;

    // ---- warm group: r[t0-32 .. t0-1] for every chunk (coalesced) -> T0 ----
    {
        const int tb = lane - 32;
#pragma unroll 8
        for (int c = 0; c < NCHUNK; c++) {
            int t = c * CHUNK + tb;
            T0[c][lane] = (t >= 0) ? __ldg(rrow + t) : 0.0f;
        }
    }
    __syncwarp();
#pragma unroll
    for (int j = 0; j < 32; j++) Abuf[j] = T0[lane][j];
    // prefetch group 1 inputs -> T1 (overlaps warm FIR below)
#pragma unroll 8
    for (int c = 0; c < NCHUNK; c++)
        T1[c][lane] = __ldg(rrow + c * CHUNK + lane);
    // warm-start FIR: y = outlet at t0-1 (raw-input units; scale applied at STG)
    {
        float s = 0.0f;
#pragma unroll
        for (int j = 12; j < 32; j++) s += Abuf[j];                 // lags 0..19
        float s2 = 0.0f;
#pragma unroll
        for (int j = 0; j < 12; j++) s2 = fmaf(GW[11 - j], Abuf[j], s2);  // 20..31
        y = s + s2;
    }
    __syncwarp();

    // ---- 4 pipelined groups of 32 steps ----
    GROUP_BODY(Abuf, Bbuf, T1, T0, 1, 1);      // compute G1, prefetch G2 -> T0
    __syncwarp(); DRAIN(T1, 1); __syncwarp();

    GROUP_BODY(Bbuf, Abuf, T0, T1, 2, 1);      // compute G2, prefetch G3 -> T1
    __syncwarp(); DRAIN(T0, 2); __syncwarp();

    GROUP_BODY(Abuf, Bbuf, T1, T0, 3, 1);      // compute G3, prefetch G4 -> T0
    __syncwarp(); DRAIN(T1, 3); __syncwarp();

    GROUP_BODY(Bbuf, Abuf, T0, T1, 4, 0);      // compute G4 (no prefetch)
    __syncwarp(); DRAIN(T0, 4);
}

extern "C" void kernel_launch(void* const* d_in, const int* in_sizes, int n_in,
                              void* d_out, int out_size)
{
    const float* runoff = (const float*)d_in[0];   // (B, T) float32
    const float* basin  = (const float*)d_in[1];   // (B, 1) float32
    float* out = (float*)d_out;                    // (B, T) float32

    int B = in_sizes[1];                           // 8192
    int blocks = (B + RPB - 1) / RPB;              // 2048
    kinematic_wave_kernel<<<blocks, 128>>>(runoff, basin, out, B);
}